// round 5
// baseline (speedup 1.0000x reference)
#include <cuda_runtime.h>
#include <math.h>

#define NN 100000
#define D1 128
#define D2 64
#define EMAX 4000000
#define SCAN_BLK 1024
#define MAXNB 128

typedef unsigned long long ull;

// ---------------- scratch (static __device__ — no runtime allocation) ----------------
__device__ float g_dis[NN];                         // rsqrt(deg+1)
__device__ int   g_deg[NN];                         // in-degree (real edges only)
__device__ int   g_rowstart[NN];                    // CSR row offsets
__device__ int   g_cursor[NN];                      // fill cursors
__device__ int   g_csr[EMAX];                       // CSR column (src) indices
__device__ int   g_blocksum[MAXNB];
__device__ int   g_blockoff[MAXNB];
__device__ float g_H1[(size_t)NN * D1];             // x @ W1 (unscaled)
__device__ float g_A1[(size_t)NN * D1];             // aggregated layer-1
__device__ float g_H2[(size_t)NN * D2];             // relu(A1+b1) @ W2 (unscaled)
__device__ float g_A2[(size_t)NN * D2];             // aggregated layer-2
__device__ int   g_is64;                            // edge_index dtype flag

// ---------------- f32x2 helpers (Blackwell packed fp32) ----------------
__device__ __forceinline__ ull pack2(float lo, float hi) {
    ull r; asm("mov.b64 %0, {%1,%2};" : "=l"(r) : "f"(lo), "f"(hi)); return r;
}
__device__ __forceinline__ float2 unpack2(ull u) {
    float2 f; asm("mov.b64 {%0,%1}, %2;" : "=f"(f.x), "=f"(f.y) : "l"(u)); return f;
}
__device__ __forceinline__ void ffma2(ull& d, ull a, ull b, ull c) {
    asm("fma.rn.f32x2 %0, %1, %2, %3;" : "=l"(d) : "l"(a), "l"(b), "l"(c));
}
__device__ __forceinline__ void fmul2(ull& d, ull a, ull b) {
    asm("mul.rn.f32x2 %0, %1, %2;" : "=l"(d) : "l"(a), "l"(b));
}

__device__ __forceinline__ int load_idx(const void* ei, long long pos, int is64) {
    return is64 ? (int)((const long long*)ei)[pos] : ((const int*)ei)[pos];
}

// ---------------- setup: dtype detect + zero degree ----------------
__global__ void setup_kernel(const unsigned int* ei, int n) {
    int i = blockIdx.x * blockDim.x + threadIdx.x;
    if (i < n) g_deg[i] = 0;
    if (blockIdx.x == 0) {
        __shared__ int any;
        if (threadIdx.x == 0) any = 0;
        __syncthreads();
        int local = 0;
        for (int j = threadIdx.x; j < 2048; j += blockDim.x)
            if (ei[2 * j + 1] != 0u) local = 1;
        if (local) any = 1;
        __syncthreads();
        if (threadIdx.x == 0) g_is64 = (any == 0) ? 1 : 0;
    }
}

__global__ void count_kernel(const void* __restrict__ ei, long long E) {
    long long e = (long long)blockIdx.x * blockDim.x + threadIdx.x;
    if (e >= E) return;
    int dst = load_idx(ei, E + e, g_is64);
    atomicAdd(&g_deg[dst], 1);
}

// ---- 2-level exclusive scan over g_deg -> rowstart/cursor; also dis ----
__global__ void scanA_kernel(int n) {
    __shared__ int s[SCAN_BLK];
    int i = blockIdx.x * SCAN_BLK + threadIdx.x;
    s[threadIdx.x] = (i < n) ? g_deg[i] : 0;
    __syncthreads();
    for (int off = SCAN_BLK / 2; off > 0; off >>= 1) {
        if (threadIdx.x < off) s[threadIdx.x] += s[threadIdx.x + off];
        __syncthreads();
    }
    if (threadIdx.x == 0) g_blocksum[blockIdx.x] = s[0];
}

__global__ void scanB_kernel(int nb) {
    __shared__ int s[MAXNB];
    int v = (threadIdx.x < nb) ? g_blocksum[threadIdx.x] : 0;
    s[threadIdx.x] = v;
    __syncthreads();
    for (int off = 1; off < MAXNB; off <<= 1) {
        int t = (threadIdx.x >= off) ? s[threadIdx.x - off] : 0;
        __syncthreads();
        s[threadIdx.x] += t;
        __syncthreads();
    }
    if (threadIdx.x < nb) g_blockoff[threadIdx.x] = s[threadIdx.x] - v;
}

__global__ void scanC_kernel(int n) {
    __shared__ int s[SCAN_BLK];
    int i = blockIdx.x * SCAN_BLK + threadIdx.x;
    int v = (i < n) ? g_deg[i] : 0;
    s[threadIdx.x] = v;
    __syncthreads();
    for (int off = 1; off < SCAN_BLK; off <<= 1) {
        int t = (threadIdx.x >= off) ? s[threadIdx.x - off] : 0;
        __syncthreads();
        s[threadIdx.x] += t;
        __syncthreads();
    }
    if (i < n) {
        int excl = s[threadIdx.x] - v + g_blockoff[blockIdx.x];
        g_rowstart[i] = excl;
        g_cursor[i] = excl;
        g_dis[i] = rsqrtf((float)(v + 1));
    }
}

__global__ void fill_kernel(const void* __restrict__ ei, long long E) {
    long long e = (long long)blockIdx.x * blockDim.x + threadIdx.x;
    if (e >= E) return;
    const int is64 = g_is64;
    int src = load_idx(ei, e, is64);
    int dst = load_idx(ei, E + e, is64);
    int pos = atomicAdd(&g_cursor[dst], 1);
    g_csr[pos] = src;
}

// ---------------- GEMM (f32x2): H = X@W  (optionally relu(X+bin) on load) ----------
// IN=128. OUT is 128 (2 packed col-pairs/lane) or 64 (1 pair).
template <int OUT, bool RELU_IN>
__global__ void gemm_kernel(const float* __restrict__ X, const float* __restrict__ W,
                            const float* __restrict__ bin,
                            float* __restrict__ H, int n) {
    constexpr int IN = 128;
    constexpr int PPL = OUT / 64;   // packed col-pairs per lane (2 or 1)
    extern __shared__ float smem[];
    float* Ws = smem;                                                 // IN*OUT floats
    float2* xs = (float2*)(smem + IN * OUT) + (threadIdx.x >> 5) * (4 * IN); // dup-stage
    const ull* xsu_base = (const ull*)xs;
    const int lane = threadIdx.x & 31;

    for (int i = threadIdx.x; i < IN * OUT; i += blockDim.x) Ws[i] = W[i];
    __syncthreads();

    for (int it = 0; it < 4; ++it) {
        const int r0 = blockIdx.x * 128 + it * 32 + (threadIdx.x >> 5) * 4;
        if (r0 >= n) break;

        // stage 4 rows, each value duplicated {x,x} for packed broadcast
        #pragma unroll
        for (int j = 0; j < 4; ++j) {
            const int row = r0 + j;
            float4 v = make_float4(0.f, 0.f, 0.f, 0.f);
            if (row < n) {
                v = *(const float4*)&X[(size_t)row * IN + lane * 4];
                if (RELU_IN) {
                    const float4 b = *(const float4*)&bin[lane * 4];
                    v.x = fmaxf(v.x + b.x, 0.f);
                    v.y = fmaxf(v.y + b.y, 0.f);
                    v.z = fmaxf(v.z + b.z, 0.f);
                    v.w = fmaxf(v.w + b.w, 0.f);
                }
            }
            xs[j * IN + lane * 4 + 0] = make_float2(v.x, v.x);
            xs[j * IN + lane * 4 + 1] = make_float2(v.y, v.y);
            xs[j * IN + lane * 4 + 2] = make_float2(v.z, v.z);
            xs[j * IN + lane * 4 + 3] = make_float2(v.w, v.w);
        }
        __syncwarp();

        ull acc[4][PPL];
        #pragma unroll
        for (int j = 0; j < 4; ++j)
            #pragma unroll
            for (int p = 0; p < PPL; ++p) acc[j][p] = 0ull;

        #pragma unroll 4
        for (int k = 0; k < IN; ++k) {
            ull wq[PPL];
            if (PPL == 2) {
                const ulonglong2 w2 = *(const ulonglong2*)&Ws[k * OUT + lane * 4];
                wq[0] = w2.x; wq[1] = w2.y;
            } else {
                wq[0] = *(const ull*)&Ws[k * OUT + lane * 2];
            }
            #pragma unroll
            for (int j = 0; j < 4; ++j) {
                const ull xv = xsu_base[j * IN + k];
                #pragma unroll
                for (int p = 0; p < PPL; ++p) ffma2(acc[j][p], xv, wq[p], acc[j][p]);
            }
        }
        __syncwarp();

        #pragma unroll
        for (int j = 0; j < 4; ++j) {
            const int row = r0 + j;
            if (row >= n) continue;
            if (PPL == 2) {
                const float2 a = unpack2(acc[j][0]);
                const float2 b = unpack2(acc[j][1]);
                *(float4*)&H[(size_t)row * OUT + lane * 4] = make_float4(a.x, a.y, b.x, b.y);
            } else {
                const float2 a = unpack2(acc[j][0]);
                *(float2*)&H[(size_t)row * OUT + lane * 2] = a;
            }
        }
    }
}

// -------- gather: A[d] = dis[d] * ( dis[d]*H[d] + sum_{s in N(d)} dis[s]*H[s] ) ------
template <int D>
__global__ void gather_kernel(const float* __restrict__ H, float* __restrict__ A, int n) {
    constexpr int LPN = D / 4;
    const long long gt = (long long)blockIdx.x * blockDim.x + threadIdx.x;
    const int node = (int)(gt / LPN);
    const int l = (int)(gt % LPN);
    if (node >= n) return;

    const float4* __restrict__ h4 = (const float4*)H;
    const size_t col = (size_t)node * LPN + l;
    const float d = g_dis[node];
    const ull dd = pack2(d, d);

    // self term: dis[d]*H[d]
    float4 sv = h4[col];
    ull acc0, acc1;
    fmul2(acc0, pack2(sv.x, sv.y), dd);
    fmul2(acc1, pack2(sv.z, sv.w), dd);

    const int beg = g_rowstart[node];
    const int cnt = g_deg[node];

    #pragma unroll 4
    for (int j = 0; j < cnt; ++j) {
        const int src = __ldg(&g_csr[beg + j]);
        const float s = g_dis[src];
        const ull ss = pack2(s, s);
        const float4 v = h4[(size_t)src * LPN + l];
        ffma2(acc0, pack2(v.x, v.y), ss, acc0);
        ffma2(acc1, pack2(v.z, v.w), ss, acc1);
    }

    fmul2(acc0, acc0, dd);
    fmul2(acc1, acc1, dd);
    const float2 a = unpack2(acc0);
    const float2 b = unpack2(acc1);
    ((float4*)A)[col] = make_float4(a.x, a.y, b.x, b.y);
}

// ---------------- final: out = softmax(relu(A2+b2) @ Wf + bf) ----------------
__global__ void final_kernel(const float* __restrict__ A2, const float* __restrict__ b2,
                             const float* __restrict__ Wf, const float* __restrict__ bf,
                             float* __restrict__ out, int n) {
    __shared__ float Wfs[64 * 10];
    __shared__ float bfs[10];
    __shared__ float b2s[64];
    for (int i = threadIdx.x; i < 640; i += blockDim.x) Wfs[i] = Wf[i];
    if (threadIdx.x < 10) bfs[threadIdx.x] = bf[threadIdx.x];
    if (threadIdx.x < 64) b2s[threadIdx.x] = b2[threadIdx.x];
    __syncthreads();

    const int i = blockIdx.x * blockDim.x + threadIdx.x;
    if (i >= n) return;

    float acc[10];
    #pragma unroll
    for (int c = 0; c < 10; ++c) acc[c] = bfs[c];

    #pragma unroll
    for (int kk = 0; kk < 64; kk += 4) {
        float4 v = *(const float4*)&A2[(size_t)i * 64 + kk];
        v.x = fmaxf(v.x + b2s[kk + 0], 0.f);
        v.y = fmaxf(v.y + b2s[kk + 1], 0.f);
        v.z = fmaxf(v.z + b2s[kk + 2], 0.f);
        v.w = fmaxf(v.w + b2s[kk + 3], 0.f);
        #pragma unroll
        for (int c = 0; c < 10; ++c) {
            acc[c] = fmaf(v.x, Wfs[(kk + 0) * 10 + c], acc[c]);
            acc[c] = fmaf(v.y, Wfs[(kk + 1) * 10 + c], acc[c]);
            acc[c] = fmaf(v.z, Wfs[(kk + 2) * 10 + c], acc[c]);
            acc[c] = fmaf(v.w, Wfs[(kk + 3) * 10 + c], acc[c]);
        }
    }

    float m = acc[0];
    #pragma unroll
    for (int c = 1; c < 10; ++c) m = fmaxf(m, acc[c]);
    float s = 0.f;
    float ex[10];
    #pragma unroll
    for (int c = 0; c < 10; ++c) { ex[c] = expf(acc[c] - m); s += ex[c]; }
    const float inv = 1.0f / s;
    #pragma unroll
    for (int c = 0; c < 10; ++c) out[(size_t)i * 10 + c] = ex[c] * inv;
}

// ---------------- launch ----------------
extern "C" void kernel_launch(void* const* d_in, const int* in_sizes, int n_in,
                              void* d_out, int out_size) {
    const float* x  = (const float*)d_in[0];
    const void*  ei = d_in[1];
    const float* W1 = (const float*)d_in[2];
    const float* b1 = (const float*)d_in[3];
    const float* W2 = (const float*)d_in[4];
    const float* b2 = (const float*)d_in[5];
    const float* Wf = (const float*)d_in[6];
    const float* bf = (const float*)d_in[7];
    float* out = (float*)d_out;

    const long long E = (long long)in_sizes[1] / 2;
    const int n = in_sizes[0] / D1;
    const int nb = (n + SCAN_BLK - 1) / SCAN_BLK;

    float *H1, *A1, *H2, *A2;
    cudaGetSymbolAddress((void**)&H1, g_H1);
    cudaGetSymbolAddress((void**)&A1, g_A1);
    cudaGetSymbolAddress((void**)&H2, g_H2);
    cudaGetSymbolAddress((void**)&A2, g_A2);

    // smem: Ws (IN*OUT*4B) + dup-stage (8 warps * 4 rows * 128 * 8B = 32KB)
    const int smem1 = 128 * 128 * 4 + 8 * 4 * 128 * 8;   // 98304
    const int smem2 = 128 * 64 * 4 + 8 * 4 * 128 * 8;    // 65536
    cudaFuncSetAttribute(gemm_kernel<128, false>,
                         cudaFuncAttributeMaxDynamicSharedMemorySize, smem1);
    cudaFuncSetAttribute(gemm_kernel<64, true>,
                         cudaFuncAttributeMaxDynamicSharedMemorySize, smem2);

    // Launch order puts gemm1 at index 3 (where ncu's sampler lands).
    setup_kernel<<<(n + 255) / 256, 256>>>((const unsigned int*)ei, n);
    if (E > 0) count_kernel<<<(int)((E + 255) / 256), 256>>>(ei, E);
    scanA_kernel<<<nb, SCAN_BLK>>>(n);
    gemm_kernel<128, false><<<(n + 127) / 128, 256, smem1>>>(x, W1, nullptr, H1, n);
    scanB_kernel<<<1, MAXNB>>>(nb);
    scanC_kernel<<<nb, SCAN_BLK>>>(n);
    if (E > 0) fill_kernel<<<(int)((E + 255) / 256), 256>>>(ei, E);

    gather_kernel<128><<<(int)(((long long)n * 32 + 255) / 256), 256>>>(H1, A1, n);

    gemm_kernel<64, true><<<(n + 127) / 128, 256, smem2>>>(A1, W2, b1, H2, n);
    gather_kernel<64><<<(int)(((long long)n * 16 + 255) / 256), 256>>>(H2, A2, n);

    final_kernel<<<(n + 255) / 256, 256>>>(A2, b2, Wf, bf, out, n);
}

// round 6
// speedup vs baseline: 1.1739x; 1.1739x over previous
#include <cuda_runtime.h>
#include <math.h>

#define NN 100000
#define D1 128
#define D2 64
#define EMAX 4000000
#define SCAN_BLK 1024
#define MAXNB 128

typedef unsigned long long ull;

// ---------------- scratch (static __device__ — no runtime allocation) ----------------
__device__ float g_dis[NN];                         // rsqrt(deg+1)
__device__ int   g_deg[NN];                         // in-degree (real edges only)
__device__ int   g_rowstart[NN];                    // CSR row offsets
__device__ int   g_cursor[NN];                      // fill cursors
__device__ int   g_csr[EMAX];                       // CSR column (src) indices
__device__ int   g_blocksum[MAXNB];
__device__ int   g_blockoff[MAXNB];
__device__ float g_H1[(size_t)NN * D1];             // x @ W1 (unscaled)
__device__ float g_A1[(size_t)NN * D1];             // aggregated layer-1
__device__ float g_H2[(size_t)NN * D2];             // relu(A1+b1) @ W2 (unscaled)
__device__ float g_A2[(size_t)NN * D2];             // aggregated layer-2
__device__ int   g_is64;                            // edge_index dtype flag

// ---------------- f32x2 helpers (Blackwell packed fp32) ----------------
__device__ __forceinline__ ull pack2(float lo, float hi) {
    ull r; asm("mov.b64 %0, {%1,%2};" : "=l"(r) : "f"(lo), "f"(hi)); return r;
}
__device__ __forceinline__ float2 unpack2(ull u) {
    float2 f; asm("mov.b64 {%0,%1}, %2;" : "=f"(f.x), "=f"(f.y) : "l"(u)); return f;
}
__device__ __forceinline__ void ffma2(ull& d, ull a, ull b, ull c) {
    asm("fma.rn.f32x2 %0, %1, %2, %3;" : "=l"(d) : "l"(a), "l"(b), "l"(c));
}
__device__ __forceinline__ void fmul2(ull& d, ull a, ull b) {
    asm("mul.rn.f32x2 %0, %1, %2;" : "=l"(d) : "l"(a), "l"(b));
}

__device__ __forceinline__ int load_idx(const void* ei, long long pos, int is64) {
    return is64 ? (int)((const long long*)ei)[pos] : ((const int*)ei)[pos];
}

// ---------------- setup: dtype detect + zero degree ----------------
__global__ void setup_kernel(const unsigned int* ei, int n) {
    int i = blockIdx.x * blockDim.x + threadIdx.x;
    if (i < n) g_deg[i] = 0;
    if (blockIdx.x == 0) {
        __shared__ int any;
        if (threadIdx.x == 0) any = 0;
        __syncthreads();
        int local = 0;
        for (int j = threadIdx.x; j < 2048; j += blockDim.x)
            if (ei[2 * j + 1] != 0u) local = 1;
        if (local) any = 1;
        __syncthreads();
        if (threadIdx.x == 0) g_is64 = (any == 0) ? 1 : 0;
    }
}

__global__ void count_kernel(const void* __restrict__ ei, long long E) {
    long long e = (long long)blockIdx.x * blockDim.x + threadIdx.x;
    if (e >= E) return;
    int dst = load_idx(ei, E + e, g_is64);
    atomicAdd(&g_deg[dst], 1);
}

// ---- 2-level exclusive scan over g_deg -> rowstart/cursor; also dis ----
__global__ void scanA_kernel(int n) {
    __shared__ int s[SCAN_BLK];
    int i = blockIdx.x * SCAN_BLK + threadIdx.x;
    s[threadIdx.x] = (i < n) ? g_deg[i] : 0;
    __syncthreads();
    for (int off = SCAN_BLK / 2; off > 0; off >>= 1) {
        if (threadIdx.x < off) s[threadIdx.x] += s[threadIdx.x + off];
        __syncthreads();
    }
    if (threadIdx.x == 0) g_blocksum[blockIdx.x] = s[0];
}

__global__ void scanB_kernel(int nb) {
    __shared__ int s[MAXNB];
    int v = (threadIdx.x < nb) ? g_blocksum[threadIdx.x] : 0;
    s[threadIdx.x] = v;
    __syncthreads();
    for (int off = 1; off < MAXNB; off <<= 1) {
        int t = (threadIdx.x >= off) ? s[threadIdx.x - off] : 0;
        __syncthreads();
        s[threadIdx.x] += t;
        __syncthreads();
    }
    if (threadIdx.x < nb) g_blockoff[threadIdx.x] = s[threadIdx.x] - v;
}

__global__ void scanC_kernel(int n) {
    __shared__ int s[SCAN_BLK];
    int i = blockIdx.x * SCAN_BLK + threadIdx.x;
    int v = (i < n) ? g_deg[i] : 0;
    s[threadIdx.x] = v;
    __syncthreads();
    for (int off = 1; off < SCAN_BLK; off <<= 1) {
        int t = (threadIdx.x >= off) ? s[threadIdx.x - off] : 0;
        __syncthreads();
        s[threadIdx.x] += t;
        __syncthreads();
    }
    if (i < n) {
        int excl = s[threadIdx.x] - v + g_blockoff[blockIdx.x];
        g_rowstart[i] = excl;
        g_cursor[i] = excl;
        g_dis[i] = rsqrtf((float)(v + 1));
    }
}

__global__ void fill_kernel(const void* __restrict__ ei, long long E) {
    long long e = (long long)blockIdx.x * blockDim.x + threadIdx.x;
    if (e >= E) return;
    const int is64 = g_is64;
    int src = load_idx(ei, e, is64);
    int dst = load_idx(ei, E + e, is64);
    int pos = atomicAdd(&g_cursor[dst], 1);
    g_csr[pos] = src;
}

// ---------------- register-tiled GEMM (8x8 per thread, f32x2 FMAs) ------------------
// H = X@W, optionally X <- relu(X + bin) on load. IN = 128.
// Block: 256 threads. OUT=128: 16x16 thread grid, 128-row tile.
//                     OUT=64 :  8x32 thread grid, 256-row tile.
template <int OUT, bool RELU_IN>
__global__ void __launch_bounds__(256, 2)
gemm_kernel(const float* __restrict__ X, const float* __restrict__ W,
            const float* __restrict__ bin, float* __restrict__ H, int n) {
    constexpr int IN = 128;
    constexpr int TX = OUT / 8;          // col thread-groups
    constexpr int TY = 256 / TX;         // row thread-groups
    constexpr int ROWS = TY * 8;         // rows per block tile
    constexpr int KC = 16;               // k-chunk
    constexpr int NCHUNK = IN / KC;      // 8
    constexpr int ELEMS = KC * ROWS;     // floats per xT buffer
    constexpr int PASSES = ELEMS / (256 * 4);  // float4 per thread per chunk

    extern __shared__ float smem[];
    float* Ws = smem;                    // IN*OUT
    float* xT0 = smem + IN * OUT;        // ELEMS
    float* xT1 = xT0 + ELEMS;            // ELEMS

    const int tid = threadIdx.x;
    const int tx = tid % TX;
    const int ty = tid / TX;
    const int row0 = blockIdx.x * ROWS;

    for (int i = tid; i < IN * OUT; i += 256) Ws[i] = W[i];

    float4 pf[PASSES];

    auto LOADX = [&](int kc0) {
        #pragma unroll
        for (int p = 0; p < PASSES; ++p) {
            const int idx = p * 256 + tid;
            const int r = idx >> 2;
            const int kq = idx & 3;
            const int row = row0 + r;
            float4 v = make_float4(0.f, 0.f, 0.f, 0.f);
            if (row < n) {
                v = *(const float4*)&X[(size_t)row * IN + kc0 + kq * 4];
                if (RELU_IN) {
                    const float4 b = *(const float4*)&bin[kc0 + kq * 4];
                    v.x = fmaxf(v.x + b.x, 0.f);
                    v.y = fmaxf(v.y + b.y, 0.f);
                    v.z = fmaxf(v.z + b.z, 0.f);
                    v.w = fmaxf(v.w + b.w, 0.f);
                }
            }
            pf[p] = v;
        }
    };

    auto STOREX = [&](float* buf) {
        #pragma unroll
        for (int p = 0; p < PASSES; ++p) {
            const int idx = p * 256 + tid;
            const int r = idx >> 2;
            const int kq = idx & 3;
            buf[(kq * 4 + 0) * ROWS + r] = pf[p].x;
            buf[(kq * 4 + 1) * ROWS + r] = pf[p].y;
            buf[(kq * 4 + 2) * ROWS + r] = pf[p].z;
            buf[(kq * 4 + 3) * ROWS + r] = pf[p].w;
        }
    };

    ull acc[8][4];
    #pragma unroll
    for (int j = 0; j < 8; ++j)
        #pragma unroll
        for (int p = 0; p < 4; ++p) acc[j][p] = 0ull;

    LOADX(0);
    STOREX(xT0);
    __syncthreads();

    for (int c = 0; c < NCHUNK; ++c) {
        float* cur = (c & 1) ? xT1 : xT0;
        float* nxt = (c & 1) ? xT0 : xT1;
        if (c + 1 < NCHUNK) LOADX((c + 1) * KC);

        const int kc0 = c * KC;
        #pragma unroll
        for (int kk = 0; kk < KC; ++kk) {
            const float* xr = &cur[kk * ROWS + ty * 8];
            const float4 xa = *(const float4*)xr;
            const float4 xb = *(const float4*)(xr + 4);
            ull xp[8];
            xp[0] = pack2(xa.x, xa.x); xp[1] = pack2(xa.y, xa.y);
            xp[2] = pack2(xa.z, xa.z); xp[3] = pack2(xa.w, xa.w);
            xp[4] = pack2(xb.x, xb.x); xp[5] = pack2(xb.y, xb.y);
            xp[6] = pack2(xb.z, xb.z); xp[7] = pack2(xb.w, xb.w);

            const ulonglong2* wr = (const ulonglong2*)&Ws[(kc0 + kk) * OUT + tx * 8];
            const ulonglong2 wA = wr[0];
            const ulonglong2 wB = wr[1];
            ull wq[4]; wq[0] = wA.x; wq[1] = wA.y; wq[2] = wB.x; wq[3] = wB.y;

            #pragma unroll
            for (int j = 0; j < 8; ++j) {
                ffma2(acc[j][0], xp[j], wq[0], acc[j][0]);
                ffma2(acc[j][1], xp[j], wq[1], acc[j][1]);
                ffma2(acc[j][2], xp[j], wq[2], acc[j][2]);
                ffma2(acc[j][3], xp[j], wq[3], acc[j][3]);
            }
        }

        if (c + 1 < NCHUNK) STOREX(nxt);
        __syncthreads();
    }

    #pragma unroll
    for (int j = 0; j < 8; ++j) {
        const int row = row0 + ty * 8 + j;
        if (row >= n) continue;
        const float2 a0 = unpack2(acc[j][0]);
        const float2 a1 = unpack2(acc[j][1]);
        const float2 a2 = unpack2(acc[j][2]);
        const float2 a3 = unpack2(acc[j][3]);
        float* hp = &H[(size_t)row * OUT + tx * 8];
        *(float4*)hp = make_float4(a0.x, a0.y, a1.x, a1.y);
        *(float4*)(hp + 4) = make_float4(a2.x, a2.y, a3.x, a3.y);
    }
}

// -------- gather: A[d] = dis[d] * ( dis[d]*H[d] + sum_{s in N(d)} dis[s]*H[s] ) ------
template <int D>
__global__ void gather_kernel(const float* __restrict__ H, float* __restrict__ A, int n) {
    constexpr int LPN = D / 4;
    const long long gt = (long long)blockIdx.x * blockDim.x + threadIdx.x;
    const int node = (int)(gt / LPN);
    const int l = (int)(gt % LPN);
    if (node >= n) return;

    const float4* __restrict__ h4 = (const float4*)H;
    const size_t col = (size_t)node * LPN + l;
    const float d = g_dis[node];
    const ull dd = pack2(d, d);

    float4 sv = h4[col];
    ull acc0, acc1;
    fmul2(acc0, pack2(sv.x, sv.y), dd);
    fmul2(acc1, pack2(sv.z, sv.w), dd);

    const int beg = g_rowstart[node];
    const int cnt = g_deg[node];

    #pragma unroll 4
    for (int j = 0; j < cnt; ++j) {
        const int src = __ldg(&g_csr[beg + j]);
        const float s = g_dis[src];
        const ull ss = pack2(s, s);
        const float4 v = h4[(size_t)src * LPN + l];
        ffma2(acc0, pack2(v.x, v.y), ss, acc0);
        ffma2(acc1, pack2(v.z, v.w), ss, acc1);
    }

    fmul2(acc0, acc0, dd);
    fmul2(acc1, acc1, dd);
    const float2 a = unpack2(acc0);
    const float2 b = unpack2(acc1);
    ((float4*)A)[col] = make_float4(a.x, a.y, b.x, b.y);
}

// ---------------- final: out = softmax(relu(A2+b2) @ Wf + bf) ----------------
__global__ void final_kernel(const float* __restrict__ A2, const float* __restrict__ b2,
                             const float* __restrict__ Wf, const float* __restrict__ bf,
                             float* __restrict__ out, int n) {
    __shared__ float Wfs[64 * 10];
    __shared__ float bfs[10];
    __shared__ float b2s[64];
    for (int i = threadIdx.x; i < 640; i += blockDim.x) Wfs[i] = Wf[i];
    if (threadIdx.x < 10) bfs[threadIdx.x] = bf[threadIdx.x];
    if (threadIdx.x < 64) b2s[threadIdx.x] = b2[threadIdx.x];
    __syncthreads();

    const int i = blockIdx.x * blockDim.x + threadIdx.x;
    if (i >= n) return;

    float acc[10];
    #pragma unroll
    for (int c = 0; c < 10; ++c) acc[c] = bfs[c];

    #pragma unroll
    for (int kk = 0; kk < 64; kk += 4) {
        float4 v = *(const float4*)&A2[(size_t)i * 64 + kk];
        v.x = fmaxf(v.x + b2s[kk + 0], 0.f);
        v.y = fmaxf(v.y + b2s[kk + 1], 0.f);
        v.z = fmaxf(v.z + b2s[kk + 2], 0.f);
        v.w = fmaxf(v.w + b2s[kk + 3], 0.f);
        #pragma unroll
        for (int c = 0; c < 10; ++c) {
            acc[c] = fmaf(v.x, Wfs[(kk + 0) * 10 + c], acc[c]);
            acc[c] = fmaf(v.y, Wfs[(kk + 1) * 10 + c], acc[c]);
            acc[c] = fmaf(v.z, Wfs[(kk + 2) * 10 + c], acc[c]);
            acc[c] = fmaf(v.w, Wfs[(kk + 3) * 10 + c], acc[c]);
        }
    }

    float m = acc[0];
    #pragma unroll
    for (int c = 1; c < 10; ++c) m = fmaxf(m, acc[c]);
    float s = 0.f;
    float ex[10];
    #pragma unroll
    for (int c = 0; c < 10; ++c) { ex[c] = expf(acc[c] - m); s += ex[c]; }
    const float inv = 1.0f / s;
    #pragma unroll
    for (int c = 0; c < 10; ++c) out[(size_t)i * 10 + c] = ex[c] * inv;
}

// ---------------- launch ----------------
extern "C" void kernel_launch(void* const* d_in, const int* in_sizes, int n_in,
                              void* d_out, int out_size) {
    const float* x  = (const float*)d_in[0];
    const void*  ei = d_in[1];
    const float* W1 = (const float*)d_in[2];
    const float* b1 = (const float*)d_in[3];
    const float* W2 = (const float*)d_in[4];
    const float* b2 = (const float*)d_in[5];
    const float* Wf = (const float*)d_in[6];
    const float* bf = (const float*)d_in[7];
    float* out = (float*)d_out;

    const long long E = (long long)in_sizes[1] / 2;
    const int n = in_sizes[0] / D1;
    const int nb = (n + SCAN_BLK - 1) / SCAN_BLK;

    float *H1, *A1, *H2, *A2;
    cudaGetSymbolAddress((void**)&H1, g_H1);
    cudaGetSymbolAddress((void**)&A1, g_A1);
    cudaGetSymbolAddress((void**)&H2, g_H2);
    cudaGetSymbolAddress((void**)&A2, g_A2);

    // smem: Ws + 2 k-chunk xT buffers
    const int smem1 = 128 * 128 * 4 + 2 * 16 * 128 * 4;   // 81920
    const int smem2 = 128 * 64 * 4 + 2 * 16 * 256 * 4;    // 65536
    cudaFuncSetAttribute(gemm_kernel<128, false>,
                         cudaFuncAttributeMaxDynamicSharedMemorySize, smem1);
    cudaFuncSetAttribute(gemm_kernel<64, true>,
                         cudaFuncAttributeMaxDynamicSharedMemorySize, smem2);

    // gemm1 stays at launch index 3 (ncu capture slot).
    setup_kernel<<<(n + 255) / 256, 256>>>((const unsigned int*)ei, n);
    if (E > 0) count_kernel<<<(int)((E + 255) / 256), 256>>>(ei, E);
    scanA_kernel<<<nb, SCAN_BLK>>>(n);
    gemm_kernel<128, false><<<(n + 127) / 128, 256, smem1>>>(x, W1, nullptr, H1, n);
    scanB_kernel<<<1, MAXNB>>>(nb);
    scanC_kernel<<<nb, SCAN_BLK>>>(n);
    if (E > 0) fill_kernel<<<(int)((E + 255) / 256), 256>>>(ei, E);

    gather_kernel<128><<<(int)(((long long)n * 32 + 255) / 256), 256>>>(H1, A1, n);

    gemm_kernel<64, true><<<(n + 255) / 256, 256, smem2>>>(A1, W2, b1, H2, n);
    gather_kernel<64><<<(int)(((long long)n * 16 + 255) / 256), 256>>>(H2, A2, n);

    final_kernel<<<(n + 255) / 256, 256>>>(A2, b2, Wf, bf, out, n);
}